// round 1
// baseline (speedup 1.0000x reference)
#include <cuda_runtime.h>
#include <math.h>

#define BDIM 8192
#define MDIM 256
#define NSLICE 4
#define JSPAN (BDIM / NSLICE)   // 2048
#define BM 128
#define BN 128
#define BK 8

// ---- device scratch (no allocations allowed) ----
__device__ float g_hz[BDIM * MDIM];          // 8 MB  normalized z
__device__ float g_hy[BDIM * MDIM];          // 8 MB  normalized y
__device__ float g_Ssuf[MDIM * MDIM];        // suffix sums: Ssuf[j*M + k] = sum_{j'>=j} E[k][j']
__device__ float g_diag[BDIM];               // raw dot(hz_i, hy_i)
__device__ float g_pmax[NSLICE * BDIM];
__device__ float g_psum[NSLICE * BDIM];

// ---------------------------------------------------------------------------
// Kernel 1: suffix sums of E rows (for the censoring term mask @ E.T)
// grid = MDIM (k = row of E), block = MDIM threads (j)
// ---------------------------------------------------------------------------
__global__ void suffix_kernel(const float* __restrict__ E) {
    __shared__ float row[MDIM];
    int k = blockIdx.x;
    int j = threadIdx.x;
    row[j] = E[k * MDIM + j];
    __syncthreads();
    float s = 0.f;
    for (int jj = MDIM - 1; jj >= j; --jj) s += row[jj];
    g_Ssuf[j * MDIM + k] = s;
}

// ---------------------------------------------------------------------------
// block-wide sum reduction for 256 threads (8 warps)
// ---------------------------------------------------------------------------
__device__ __forceinline__ float blockReduceSum(float v, float* red) {
    __syncthreads();   // protect red reuse across calls
    #pragma unroll
    for (int o = 16; o; o >>= 1) v += __shfl_xor_sync(0xffffffffu, v, o);
    int w = threadIdx.x >> 5;
    if ((threadIdx.x & 31) == 0) red[w] = v;
    __syncthreads();
    float r = 0.f;
    if (threadIdx.x < 32) {
        r = (threadIdx.x < 8) ? red[threadIdx.x] : 0.f;
        #pragma unroll
        for (int o = 4; o; o >>= 1) r += __shfl_xor_sync(0xffffffffu, r, o);
        if (threadIdx.x == 0) red[0] = r;
    }
    __syncthreads();
    return red[0];
}

// ---------------------------------------------------------------------------
// Kernel 2: per-row prep — time interpolation, normalize y and z, diag dot.
// grid = BDIM blocks, block = MDIM threads (k = feature index)
// ---------------------------------------------------------------------------
__global__ void prep_kernel(const float* __restrict__ z,
                            const float* __restrict__ t,
                            const float* __restrict__ e,
                            const float* __restrict__ E,
                            const float* __restrict__ L) {
    __shared__ float sL[MDIM];
    __shared__ float red[8];
    int i = blockIdx.x;
    int k = threadIdx.x;
    sL[k] = L[k];
    __syncthreads();

    float ti = t[i];
    // searchsorted(L, t) side='left' : lower_bound
    int lo = 0, hi = MDIM;
    while (lo < hi) {
        int mid = (lo + hi) >> 1;
        if (sL[mid] < ti) lo = mid + 1; else hi = mid;
    }
    int idx = lo;
    if (idx == 0) idx = 1;
    if (idx == MDIM) idx = MDIM - 1;

    float Llo = sL[idx - 1], Lhi = sL[idx];
    float Elo = E[(idx - 1) * MDIM + k];
    float Ehi = E[idx * MDIM + k];
    float y_interp = Elo + (Ehi - Elo) / (Lhi - Llo) * (ti - Llo);
    float y_cens   = g_Ssuf[idx * MDIM + k] / (float)(MDIM - idx);
    float ei = e[i];
    float y = y_interp * ei + y_cens * (1.f - ei);

    float zv = z[i * MDIM + k];

    float sy = blockReduceSum(y * y, red);
    float ry = 1.f / fmaxf(sqrtf(sy), 1e-12f);
    float hy = y * ry;

    float sz = blockReduceSum(zv * zv, red);
    float rz = 1.f / fmaxf(sqrtf(sz), 1e-12f);
    float hz = zv * rz;

    float d = blockReduceSum(hz * hy, red);

    g_hy[i * MDIM + k] = hy;
    g_hz[i * MDIM + k] = hz;
    if (k == 0) g_diag[i] = d;
}

// ---------------------------------------------------------------------------
// Kernel 3: fused sim GEMM + online logsumexp.
// Each block: one 128-row panel (blockIdx.y), one j-slice of 2048 (blockIdx.x).
// 256 threads, 8x8 register tile per thread, BK=8.
// ---------------------------------------------------------------------------
__global__ __launch_bounds__(256, 2)
void gemm_lse_kernel(const float* __restrict__ log_tau) {
    __shared__ float As[BK][BM];
    __shared__ float Bs[BK][BN];
    __shared__ float redM[BM][17];
    __shared__ float redS[BM][17];

    int tid = threadIdx.x;
    int tx = tid & 15;         // 0..15  -> cols
    int ty = tid >> 4;         // 0..15  -> rows
    int panel = blockIdx.y;
    int slice = blockIdx.x;
    int row0 = panel * BM;

    float inv_tau2 = __expf(-log_tau[0]);

    int lr  = tid >> 1;         // 0..127 tile row for loads
    int lk4 = (tid & 1) * 4;    // 0 or 4 k-offset for float4 loads

    float runm[8], runs[8];
    #pragma unroll
    for (int r = 0; r < 8; r++) { runm[r] = -INFINITY; runs[r] = 0.f; }

    const float* Aptr = g_hz + (size_t)row0 * MDIM;

    for (int jt = 0; jt < JSPAN; jt += BN) {
        int col0 = slice * JSPAN + jt;
        const float* Bptr = g_hy + (size_t)col0 * MDIM;

        float acc[8][8];
        #pragma unroll
        for (int r = 0; r < 8; r++)
            #pragma unroll
            for (int c = 0; c < 8; c++) acc[r][c] = 0.f;

        for (int kk = 0; kk < MDIM; kk += BK) {
            float4 av = *(const float4*)(Aptr + lr * MDIM + kk + lk4);
            float4 bv = *(const float4*)(Bptr + lr * MDIM + kk + lk4);
            __syncthreads();
            As[lk4 + 0][lr] = av.x; As[lk4 + 1][lr] = av.y;
            As[lk4 + 2][lr] = av.z; As[lk4 + 3][lr] = av.w;
            Bs[lk4 + 0][lr] = bv.x; Bs[lk4 + 1][lr] = bv.y;
            Bs[lk4 + 2][lr] = bv.z; Bs[lk4 + 3][lr] = bv.w;
            __syncthreads();
            #pragma unroll
            for (int k = 0; k < BK; k++) {
                float a[8], b[8];
                #pragma unroll
                for (int r = 0; r < 8; r++) a[r] = As[k][ty * 8 + r];
                #pragma unroll
                for (int c = 0; c < 8; c++) b[c] = Bs[k][tx * 8 + c];
                #pragma unroll
                for (int r = 0; r < 8; r++)
                    #pragma unroll
                    for (int c = 0; c < 8; c++)
                        acc[r][c] += a[r] * b[c];
            }
        }

        // online logsumexp update per row
        #pragma unroll
        for (int r = 0; r < 8; r++) {
            float vals[8];
            float lm = -INFINITY;
            #pragma unroll
            for (int c = 0; c < 8; c++) {
                float v = acc[r][c] * inv_tau2;
                vals[c] = v;
                lm = fmaxf(lm, v);
            }
            float nm = fmaxf(runm[r], lm);
            float ssum = 0.f;
            #pragma unroll
            for (int c = 0; c < 8; c++) ssum += __expf(vals[c] - nm);
            runs[r] = runs[r] * __expf(runm[r] - nm) + ssum;
            runm[r] = nm;
        }
    }

    // reduce across the 16 tx-threads sharing each row
    __syncthreads();
    #pragma unroll
    for (int r = 0; r < 8; r++) {
        redM[ty * 8 + r][tx] = runm[r];
        redS[ty * 8 + r][tx] = runs[r];
    }
    __syncthreads();
    if (tid < BM) {
        float M = -INFINITY;
        #pragma unroll
        for (int x = 0; x < 16; x++) M = fmaxf(M, redM[tid][x]);
        float S = 0.f;
        #pragma unroll
        for (int x = 0; x < 16; x++) S += redS[tid][x] * __expf(redM[tid][x] - M);
        g_pmax[slice * BDIM + row0 + tid] = M;
        g_psum[slice * BDIM + row0 + tid] = S;
    }
}

// ---------------------------------------------------------------------------
// Kernel 4: combine slices, finalize output.
// out[i] = lse_j(sim[i,j]) - sim[i,i] - log(B), clipped to [-5, 15]
// ---------------------------------------------------------------------------
__global__ void final_kernel(const float* __restrict__ log_tau,
                             float* __restrict__ out) {
    int i = blockIdx.x * blockDim.x + threadIdx.x;
    if (i >= BDIM) return;
    float M = -INFINITY;
    #pragma unroll
    for (int s = 0; s < NSLICE; s++) M = fmaxf(M, g_pmax[s * BDIM + i]);
    float S = 0.f;
    #pragma unroll
    for (int s = 0; s < NSLICE; s++)
        S += g_psum[s * BDIM + i] * __expf(g_pmax[s * BDIM + i] - M);
    float inv_tau2 = expf(-log_tau[0]);
    float lse = M + logf(S);
    float o = lse - g_diag[i] * inv_tau2 - logf((float)BDIM);
    o = fminf(fmaxf(o, -5.f), 15.f);
    out[i] = o;
}

// ---------------------------------------------------------------------------
extern "C" void kernel_launch(void* const* d_in, const int* in_sizes, int n_in,
                              void* d_out, int out_size) {
    const float* z       = (const float*)d_in[0];
    const float* t       = (const float*)d_in[1];
    const float* e       = (const float*)d_in[2];
    const float* log_tau = (const float*)d_in[3];
    const float* E       = (const float*)d_in[4];
    const float* L       = (const float*)d_in[5];
    float* out = (float*)d_out;

    suffix_kernel<<<MDIM, MDIM>>>(E);
    prep_kernel<<<BDIM, MDIM>>>(z, t, e, E, L);
    dim3 grid(NSLICE, BDIM / BM);
    gemm_lse_kernel<<<grid, 256>>>(log_tau);
    final_kernel<<<BDIM / 256, 256>>>(log_tau, out);
}

// round 6
// speedup vs baseline: 6.6621x; 6.6621x over previous
#include <cuda_runtime.h>
#include <cuda_bf16.h>
#include <cstdint>
#include <math.h>

#define BDIM 8192
#define MDIM 256
#define NSLICE 2
#define JSPAN (BDIM / NSLICE)   // 4096
#define GBM 128
#define GBN 128
#define TILES (JSPAN / GBN)     // 32

#define A_STRIDE 264                     // bf16 elems per smem row (256 + 8 pad)
#define A_STRIDE_B (A_STRIDE * 2)        // 528 bytes
#define TILE_BYTES (GBM * A_STRIDE_B)    // 67584

// ---- device scratch (no allocations allowed) ----
__device__ __align__(16) __nv_bfloat16 g_hzb[BDIM * MDIM];  // bf16(hz * inv_tau2)
__device__ __align__(16) __nv_bfloat16 g_hyb[BDIM * MDIM];  // bf16(hy)
__device__ float g_Ssuf[MDIM * MDIM];
__device__ float g_diag[BDIM];
__device__ float g_psum[NSLICE * BDIM];

// ============================ PTX helpers ============================
__device__ __forceinline__ uint32_t smem_u32(const void* p) {
    uint32_t a;
    asm("{ .reg .u64 t; cvta.to.shared.u64 t, %1; cvt.u32.u64 %0, t; }" : "=r"(a) : "l"(p));
    return a;
}
__device__ __forceinline__ void ldmatrix_x4(uint32_t* r, uint32_t addr) {
    asm volatile("ldmatrix.sync.aligned.m8n8.x4.shared.b16 {%0,%1,%2,%3}, [%4];"
                 : "=r"(r[0]), "=r"(r[1]), "=r"(r[2]), "=r"(r[3]) : "r"(addr));
}
__device__ __forceinline__ void mma_16816(float* c, const uint32_t* a,
                                          uint32_t b0, uint32_t b1) {
    asm volatile(
        "mma.sync.aligned.m16n8k16.row.col.f32.bf16.bf16.f32 "
        "{%0,%1,%2,%3}, {%4,%5,%6,%7}, {%8,%9}, {%0,%1,%2,%3};"
        : "+f"(c[0]), "+f"(c[1]), "+f"(c[2]), "+f"(c[3])
        : "r"(a[0]), "r"(a[1]), "r"(a[2]), "r"(a[3]), "r"(b0), "r"(b1));
}
__device__ __forceinline__ float ex2f(float x) {
    float y;
    asm("ex2.approx.ftz.f32 %0, %1;" : "=f"(y) : "f"(x));
    return y;
}
#define CP_ASYNC16(s, g) \
    asm volatile("cp.async.cg.shared.global [%0], [%1], 16;" :: "r"(s), "l"(g))
#define CP_COMMIT()  asm volatile("cp.async.commit_group;" ::: "memory")
#define CP_WAIT0()   asm volatile("cp.async.wait_group 0;" ::: "memory")

// copy 128 rows x 512B (K-major bf16) into padded smem (stride 528B)
__device__ __forceinline__ void cp_tile(const __nv_bfloat16* __restrict__ g,
                                        uint32_t s, int tid) {
    int chunk = tid & 31;          // 16B chunk within row
    int row   = tid >> 5;          // 0..7, step 8
    const char* gp = (const char*)g + (size_t)row * 512 + chunk * 16;
    uint32_t sp = s + row * A_STRIDE_B + chunk * 16;
    #pragma unroll
    for (int r = 0; r < 16; r++) {
        CP_ASYNC16(sp, gp);
        gp += 8 * 512;
        sp += 8 * A_STRIDE_B;
    }
}

// ---------------------------------------------------------------------------
// Kernel 1: suffix sums of E rows (censor term)
// ---------------------------------------------------------------------------
__global__ void suffix_kernel(const float* __restrict__ E) {
    __shared__ float row[MDIM];
    int k = blockIdx.x, j = threadIdx.x;
    row[j] = E[k * MDIM + j];
    __syncthreads();
    float s = 0.f;
    for (int jj = MDIM - 1; jj >= j; --jj) s += row[jj];
    g_Ssuf[j * MDIM + k] = s;
}

__device__ __forceinline__ float blockReduceSum(float v, float* red) {
    __syncthreads();
    #pragma unroll
    for (int o = 16; o; o >>= 1) v += __shfl_xor_sync(0xffffffffu, v, o);
    int w = threadIdx.x >> 5;
    if ((threadIdx.x & 31) == 0) red[w] = v;
    __syncthreads();
    float r = 0.f;
    if (threadIdx.x < 32) {
        r = (threadIdx.x < 8) ? red[threadIdx.x] : 0.f;
        #pragma unroll
        for (int o = 4; o; o >>= 1) r += __shfl_xor_sync(0xffffffffu, r, o);
        if (threadIdx.x == 0) red[0] = r;
    }
    __syncthreads();
    return red[0];
}

// ---------------------------------------------------------------------------
// Kernel 2: prep — interp, normalize, diag dot, bf16 convert
// ---------------------------------------------------------------------------
__global__ void prep_kernel(const float* __restrict__ z,
                            const float* __restrict__ t,
                            const float* __restrict__ e,
                            const float* __restrict__ log_tau,
                            const float* __restrict__ E,
                            const float* __restrict__ L) {
    __shared__ float sL[MDIM];
    __shared__ float red[8];
    int i = blockIdx.x, k = threadIdx.x;
    sL[k] = L[k];
    __syncthreads();

    float ti = t[i];
    int lo = 0, hi = MDIM;
    while (lo < hi) { int mid = (lo + hi) >> 1; if (sL[mid] < ti) lo = mid + 1; else hi = mid; }
    int idx = lo;
    if (idx == 0) idx = 1;
    if (idx == MDIM) idx = MDIM - 1;

    float Llo = sL[idx - 1], Lhi = sL[idx];
    float Elo = E[(idx - 1) * MDIM + k];
    float Ehi = E[idx * MDIM + k];
    float y_interp = Elo + (Ehi - Elo) / (Lhi - Llo) * (ti - Llo);
    float y_cens   = g_Ssuf[idx * MDIM + k] / (float)(MDIM - idx);
    float ei = e[i];
    float y = y_interp * ei + y_cens * (1.f - ei);
    float zv = z[i * MDIM + k];

    float sy = blockReduceSum(y * y, red);
    float hy = y * (1.f / fmaxf(sqrtf(sy), 1e-12f));
    float sz = blockReduceSum(zv * zv, red);
    float hz = zv * (1.f / fmaxf(sqrtf(sz), 1e-12f));
    float d  = blockReduceSum(hz * hy, red);

    float inv_tau2 = __expf(-log_tau[0]);
    g_hzb[i * MDIM + k] = __float2bfloat16(hz * inv_tau2);
    g_hyb[i * MDIM + k] = __float2bfloat16(hy);
    if (k == 0) g_diag[i] = d;
}

// ---------------------------------------------------------------------------
// Kernel 3: bf16 mma.sync GEMM + fixed-max exp-sum epilogue (register accums)
// grid = (NSLICE, 64), block = 256 (8 warps: 2 M x 4 N, warp tile 64x32)
// ---------------------------------------------------------------------------
__global__ __launch_bounds__(256, 1)
void gemm_lse_mma(const float* __restrict__ log_tau) {
    extern __shared__ char smem[];
    uint32_t sA  = smem_u32(smem);
    uint32_t sB0 = sA + TILE_BYTES;
    uint32_t sB1 = sB0 + TILE_BYTES;

    int tid  = threadIdx.x;
    int lane = tid & 31;
    int warp = tid >> 5;
    int warp_m = warp >> 2;     // 0..1
    int warp_n = warp & 3;      // 0..3

    int slice   = blockIdx.x;
    int row0    = blockIdx.y * GBM;
    int colbase = slice * JSPAN;

    // initial loads: A panel + B tile 0
    cp_tile(g_hzb + (size_t)row0 * MDIM,    sA,  tid);
    cp_tile(g_hyb + (size_t)colbase * MDIM, sB0, tid);
    CP_COMMIT();

    float Mconst = __expf(-log_tau[0]);   // softmax max bound: sim*inv_tau2 <= inv_tau2
    const float L2E = 1.4426950408889634f;
    float ebias = -Mconst * L2E;

    // lane-level ldmatrix addressing (offsets within tile)
    uint32_t a_off = (uint32_t)((warp_m * 64 + (lane & 15)) * A_STRIDE_B + (lane >> 4) * 16);
    uint32_t b_off = (uint32_t)((warp_n * 32 + (lane & 7) + ((lane >> 4) << 3)) * A_STRIDE_B
                                + ((lane >> 3) & 1) * 16);

    float rowsum[8];
    #pragma unroll
    for (int i = 0; i < 8; i++) rowsum[i] = 0.f;

    CP_WAIT0();
    __syncthreads();

    for (int n = 0; n < TILES; n++) {
        uint32_t sBcur = (n & 1) ? sB1 : sB0;

        // prefetch next B tile into the other buffer (its last reader was
        // tile n-1's compute, which completed before the previous barrier)
        if (n + 1 < TILES) {
            uint32_t sBnext = (n & 1) ? sB0 : sB1;
            cp_tile(g_hyb + (size_t)(colbase + (n + 1) * GBN) * MDIM, sBnext, tid);
            CP_COMMIT();
        }

        float acc[4][4][4];
        #pragma unroll
        for (int mi = 0; mi < 4; mi++)
            #pragma unroll
            for (int nj = 0; nj < 4; nj++)
                #pragma unroll
                for (int c = 0; c < 4; c++) acc[mi][nj][c] = 0.f;

        #pragma unroll
        for (int ks = 0; ks < 16; ks++) {
            uint32_t af[4][4], bf[2][4];
            #pragma unroll
            for (int mi = 0; mi < 4; mi++)
                ldmatrix_x4(af[mi], sA + a_off + mi * 16 * A_STRIDE_B + ks * 32);
            #pragma unroll
            for (int nb = 0; nb < 2; nb++)
                ldmatrix_x4(bf[nb], sBcur + b_off + nb * 16 * A_STRIDE_B + ks * 32);
            #pragma unroll
            for (int mi = 0; mi < 4; mi++)
                #pragma unroll
                for (int nj = 0; nj < 4; nj++)
                    mma_16816(acc[mi][nj], af[mi],
                              bf[nj >> 1][(nj & 1) * 2], bf[nj >> 1][(nj & 1) * 2 + 1]);
        }

        // epilogue: rowsum += exp(v - Mconst) via MUFU ex2
        #pragma unroll
        for (int mi = 0; mi < 4; mi++)
            #pragma unroll
            for (int nj = 0; nj < 4; nj++) {
                rowsum[mi * 2 + 0] += ex2f(fmaf(acc[mi][nj][0], L2E, ebias))
                                    + ex2f(fmaf(acc[mi][nj][1], L2E, ebias));
                rowsum[mi * 2 + 1] += ex2f(fmaf(acc[mi][nj][2], L2E, ebias))
                                    + ex2f(fmaf(acc[mi][nj][3], L2E, ebias));
            }

        CP_WAIT0();
        __syncthreads();
    }

    // reduce rowsums: lanes sharing a row differ in bits 0-1
    #pragma unroll
    for (int i = 0; i < 8; i++) {
        rowsum[i] += __shfl_xor_sync(0xffffffffu, rowsum[i], 1);
        rowsum[i] += __shfl_xor_sync(0xffffffffu, rowsum[i], 2);
    }
    float* red = (float*)smem;   // reuse A area (compute done)
    if ((lane & 3) == 0) {
        int g = lane >> 2;
        #pragma unroll
        for (int i = 0; i < 8; i++) {
            int row = warp_m * 64 + (i >> 1) * 16 + g + (i & 1) * 8;
            red[row * 4 + warp_n] = rowsum[i];
        }
    }
    __syncthreads();
    if (tid < GBM) {
        float s = red[tid * 4] + red[tid * 4 + 1] + red[tid * 4 + 2] + red[tid * 4 + 3];
        g_psum[slice * BDIM + row0 + tid] = s;
    }
}

// ---------------------------------------------------------------------------
// Kernel 4: combine slices, finalize
// ---------------------------------------------------------------------------
__global__ void final_kernel(const float* __restrict__ log_tau,
                             float* __restrict__ out) {
    int i = blockIdx.x * blockDim.x + threadIdx.x;
    if (i >= BDIM) return;
    float S = 0.f;
    #pragma unroll
    for (int s = 0; s < NSLICE; s++) S += g_psum[s * BDIM + i];
    float inv_tau2 = expf(-log_tau[0]);
    float o = inv_tau2 + logf(S) - g_diag[i] * inv_tau2 - logf((float)BDIM);
    out[i] = fminf(fmaxf(o, -5.f), 15.f);
}

// ---------------------------------------------------------------------------
extern "C" void kernel_launch(void* const* d_in, const int* in_sizes, int n_in,
                              void* d_out, int out_size) {
    const float* z       = (const float*)d_in[0];
    const float* t       = (const float*)d_in[1];
    const float* e       = (const float*)d_in[2];
    const float* log_tau = (const float*)d_in[3];
    const float* E       = (const float*)d_in[4];
    const float* L       = (const float*)d_in[5];
    float* out = (float*)d_out;

    const int smem_sz = 3 * TILE_BYTES;   // 202,752 B
    cudaFuncSetAttribute(gemm_lse_mma, cudaFuncAttributeMaxDynamicSharedMemorySize, smem_sz);

    suffix_kernel<<<MDIM, MDIM>>>(E);
    prep_kernel<<<BDIM, MDIM>>>(z, t, e, log_tau, E, L);
    gemm_lse_mma<<<dim3(NSLICE, BDIM / GBM), 256, smem_sz>>>(log_tau);
    final_kernel<<<BDIM / 256, 256>>>(log_tau, out);
}

// round 7
// speedup vs baseline: 8.0266x; 1.2048x over previous
#include <cuda_runtime.h>
#include <cuda_bf16.h>
#include <cstdint>
#include <math.h>

#define BDIM 8192
#define MDIM 256
#define NSLICE 2
#define JSPAN (BDIM / NSLICE)   // 4096
#define GBM 128
#define GBN 128
#define TILES (JSPAN / GBN)     // 32
#define NPANEL (BDIM / GBM)     // 64

#define A_STRIDE 264                     // bf16 elems per smem row (256 + 8 pad)
#define A_STRIDE_B (A_STRIDE * 2)        // 528 bytes
#define TILE_BYTES (GBM * A_STRIDE_B)    // 67584

// ---- device scratch (no allocations allowed) ----
__device__ __align__(16) __nv_bfloat16 g_hzb[BDIM * MDIM];  // bf16(hz * inv_tau2)
__device__ __align__(16) __nv_bfloat16 g_hyb[BDIM * MDIM];  // bf16(hy)
__device__ float g_Ssuf[MDIM * MDIM];
__device__ float g_diag[BDIM];
__device__ float g_psum[NSLICE * BDIM];
__device__ int   g_done[NPANEL];

// ============================ PTX helpers ============================
__device__ __forceinline__ uint32_t smem_u32(const void* p) {
    uint32_t a;
    asm("{ .reg .u64 t; cvta.to.shared.u64 t, %1; cvt.u32.u64 %0, t; }" : "=r"(a) : "l"(p));
    return a;
}
__device__ __forceinline__ void ldmatrix_x4(uint32_t* r, uint32_t addr) {
    asm volatile("ldmatrix.sync.aligned.m8n8.x4.shared.b16 {%0,%1,%2,%3}, [%4];"
                 : "=r"(r[0]), "=r"(r[1]), "=r"(r[2]), "=r"(r[3]) : "r"(addr));
}
__device__ __forceinline__ void mma_16816(float* c, const uint32_t* a,
                                          uint32_t b0, uint32_t b1) {
    asm volatile(
        "mma.sync.aligned.m16n8k16.row.col.f32.bf16.bf16.f32 "
        "{%0,%1,%2,%3}, {%4,%5,%6,%7}, {%8,%9}, {%0,%1,%2,%3};"
        : "+f"(c[0]), "+f"(c[1]), "+f"(c[2]), "+f"(c[3])
        : "r"(a[0]), "r"(a[1]), "r"(a[2]), "r"(a[3]), "r"(b0), "r"(b1));
}
__device__ __forceinline__ float ex2f(float x) {
    float y;
    asm("ex2.approx.ftz.f32 %0, %1;" : "=f"(y) : "f"(x));
    return y;
}
#define CP_ASYNC16(s, g) \
    asm volatile("cp.async.cg.shared.global [%0], [%1], 16;" :: "r"(s), "l"(g))
#define CP_COMMIT()  asm volatile("cp.async.commit_group;" ::: "memory")
#define CP_WAIT0()   asm volatile("cp.async.wait_group 0;" ::: "memory")

// copy 128 rows x 512B (K-major bf16) into padded smem (stride 528B), 256 threads
__device__ __forceinline__ void cp_tile(const __nv_bfloat16* __restrict__ g,
                                        uint32_t s, int tid) {
    int chunk = tid & 31;
    int row   = tid >> 5;
    const char* gp = (const char*)g + (size_t)row * 512 + chunk * 16;
    uint32_t sp = s + row * A_STRIDE_B + chunk * 16;
    #pragma unroll
    for (int r = 0; r < 16; r++) {
        CP_ASYNC16(sp, gp);
        gp += 8 * 512;
        sp += 8 * A_STRIDE_B;
    }
}

// ---------------------------------------------------------------------------
// Kernel 1: suffix sums of E rows (censor term) + zero completion counters
// ---------------------------------------------------------------------------
__global__ void suffix_kernel(const float* __restrict__ E) {
    __shared__ float row[MDIM];
    int k = blockIdx.x, j = threadIdx.x;
    if (k == 0 && j < NPANEL) g_done[j] = 0;
    row[j] = E[k * MDIM + j];
    __syncthreads();
    float s = 0.f;
    for (int jj = MDIM - 1; jj >= j; --jj) s += row[jj];
    g_Ssuf[j * MDIM + k] = s;
}

// ---------------------------------------------------------------------------
// Kernel 2: prep — one warp per row, single fused pass, no block barriers
// ---------------------------------------------------------------------------
__global__ __launch_bounds__(256)
void prep_kernel(const float* __restrict__ z,
                 const float* __restrict__ t,
                 const float* __restrict__ e,
                 const float* __restrict__ log_tau,
                 const float* __restrict__ E,
                 const float* __restrict__ L) {
    __shared__ float sL[MDIM];
    int tid = threadIdx.x;
    sL[tid] = L[tid];
    __syncthreads();

    int lane = tid & 31, warp = tid >> 5;
    int i = blockIdx.x * 8 + warp;

    float ti = t[i], ei = e[i];
    int lo = 0, hi = MDIM;
    while (lo < hi) { int mid = (lo + hi) >> 1; if (sL[mid] < ti) lo = mid + 1; else hi = mid; }
    int idx = lo;
    if (idx == 0) idx = 1;
    if (idx == MDIM) idx = MDIM - 1;

    float Llo = sL[idx - 1], Lhi = sL[idx];
    float slope_t = (ti - Llo) / (Lhi - Llo);
    float rden = 1.f / (float)(MDIM - idx);

    const float4* Elo4 = (const float4*)(E + (size_t)(idx - 1) * MDIM) + lane * 2;
    const float4* Ehi4 = (const float4*)(E + (size_t)idx * MDIM)       + lane * 2;
    const float4* Ss4  = (const float4*)(g_Ssuf + (size_t)idx * MDIM)  + lane * 2;
    const float4* z4   = (const float4*)(z + (size_t)i * MDIM)         + lane * 2;

    float yv[8], zv[8];
    float sy = 0.f, sz = 0.f, szy = 0.f;
    #pragma unroll
    for (int h = 0; h < 2; h++) {
        float4 el = Elo4[h], eh = Ehi4[h], ss = Ss4[h], zz = z4[h];
        float elc[4] = {el.x, el.y, el.z, el.w};
        float ehc[4] = {eh.x, eh.y, eh.z, eh.w};
        float ssc[4] = {ss.x, ss.y, ss.z, ss.w};
        float zzc[4] = {zz.x, zz.y, zz.z, zz.w};
        #pragma unroll
        for (int c = 0; c < 4; c++) {
            float ylin = elc[c] + (ehc[c] - elc[c]) * slope_t;
            float ycen = ssc[c] * rden;
            float y = ylin * ei + ycen * (1.f - ei);
            yv[h * 4 + c] = y;
            zv[h * 4 + c] = zzc[c];
            sy  = fmaf(y, y, sy);
            sz  = fmaf(zzc[c], zzc[c], sz);
            szy = fmaf(zzc[c], y, szy);
        }
    }
    #pragma unroll
    for (int o = 16; o; o >>= 1) {
        sy  += __shfl_xor_sync(0xffffffffu, sy,  o);
        sz  += __shfl_xor_sync(0xffffffffu, sz,  o);
        szy += __shfl_xor_sync(0xffffffffu, szy, o);
    }
    float ny = fmaxf(sqrtf(sy), 1e-12f);
    float nz = fmaxf(sqrtf(sz), 1e-12f);
    float inv_tau2 = __expf(-log_tau[0]);
    float scz = inv_tau2 / nz;
    float scy = 1.f / ny;

    uint4 hzp, hyp;
    __nv_bfloat162* hz2 = (__nv_bfloat162*)&hzp;
    __nv_bfloat162* hy2 = (__nv_bfloat162*)&hyp;
    #pragma unroll
    for (int p = 0; p < 4; p++) {
        hz2[p] = __floats2bfloat162_rn(zv[2*p] * scz, zv[2*p+1] * scz);
        hy2[p] = __floats2bfloat162_rn(yv[2*p] * scy, yv[2*p+1] * scy);
    }
    *(uint4*)(g_hzb + (size_t)i * MDIM + lane * 8) = hzp;
    *(uint4*)(g_hyb + (size_t)i * MDIM + lane * 8) = hyp;
    if (lane == 0) g_diag[i] = szy / (ny * nz);
}

// ---------------------------------------------------------------------------
// GEMM tile step: mma for tile n into accC, epilogue of accP interleaved
// ---------------------------------------------------------------------------
template <bool EPI>
__device__ __forceinline__ void tile_step(
    float (&accC)[4][4][4], float (&accP)[4][4][4], float (&rowsum)[8],
    int n, uint32_t sA, uint32_t sB0, uint32_t sB1,
    uint32_t a_off, uint32_t b_off, int colbase, int tid,
    float L2E, float ebias)
{
    #pragma unroll
    for (int mi = 0; mi < 4; mi++)
        #pragma unroll
        for (int nj = 0; nj < 4; nj++)
            #pragma unroll
            for (int c = 0; c < 4; c++) accC[mi][nj][c] = 0.f;

    if (n + 1 < TILES) {
        cp_tile(g_hyb + (size_t)(colbase + (n + 1) * GBN) * MDIM,
                ((n + 1) & 1) ? sB1 : sB0, tid);
        CP_COMMIT();
    }
    uint32_t sBcur = (n & 1) ? sB1 : sB0;

    #pragma unroll
    for (int ks = 0; ks < 16; ks++) {
        uint32_t af[4][4], bf[2][4];
        #pragma unroll
        for (int mi = 0; mi < 4; mi++)
            ldmatrix_x4(af[mi], sA + a_off + mi * 16 * A_STRIDE_B + ks * 32);
        #pragma unroll
        for (int nb = 0; nb < 2; nb++)
            ldmatrix_x4(bf[nb], sBcur + b_off + nb * 16 * A_STRIDE_B + ks * 32);
        #pragma unroll
        for (int mi = 0; mi < 4; mi++)
            #pragma unroll
            for (int nj = 0; nj < 4; nj++)
                mma_16816(accC[mi][nj], af[mi],
                          bf[nj >> 1][(nj & 1) * 2], bf[nj >> 1][(nj & 1) * 2 + 1]);
        if (EPI) {
            // 4 of the 64 prev-tile exps per ks step: MUFU overlaps tensor pipe
            #pragma unroll
            for (int q = 0; q < 4; q++) {
                int v = ks * 4 + q;
                int mi = v >> 4, nj = (v >> 2) & 3, c = v & 3;
                rowsum[mi * 2 + (c >> 1)] += ex2f(fmaf(accP[mi][nj][c], L2E, ebias));
            }
        }
    }
    CP_WAIT0();
    __syncthreads();
}

// ---------------------------------------------------------------------------
// Kernel 3: bf16 mma.sync GEMM + pipelined exp-sum epilogue + merged finalize
// grid = (NSLICE, 64), block = 256 (8 warps: 2 M x 4 N, warp tile 64x32)
// ---------------------------------------------------------------------------
__global__ __launch_bounds__(256, 1)
void gemm_lse_mma(const float* __restrict__ log_tau, float* __restrict__ out) {
    extern __shared__ char smem[];
    __shared__ int s_last;
    uint32_t sA  = smem_u32(smem);
    uint32_t sB0 = sA + TILE_BYTES;
    uint32_t sB1 = sB0 + TILE_BYTES;

    int tid  = threadIdx.x;
    int lane = tid & 31;
    int warp = tid >> 5;
    int warp_m = warp >> 2;
    int warp_n = warp & 3;

    int slice   = blockIdx.x;
    int panel   = blockIdx.y;
    int row0    = panel * GBM;
    int colbase = slice * JSPAN;

    cp_tile(g_hzb + (size_t)row0 * MDIM,    sA,  tid);
    cp_tile(g_hyb + (size_t)colbase * MDIM, sB0, tid);
    CP_COMMIT();

    float Mconst = __expf(-log_tau[0]);
    const float L2E = 1.4426950408889634f;
    float ebias = -Mconst * L2E;

    uint32_t a_off = (uint32_t)((warp_m * 64 + (lane & 15)) * A_STRIDE_B + (lane >> 4) * 16);
    uint32_t b_off = (uint32_t)((warp_n * 32 + (lane & 7) + ((lane >> 4) << 3)) * A_STRIDE_B
                                + ((lane >> 3) & 1) * 16);

    float rowsum[8];
    #pragma unroll
    for (int i = 0; i < 8; i++) rowsum[i] = 0.f;

    float acc0[4][4][4], acc1[4][4][4];

    CP_WAIT0();
    __syncthreads();

    // software pipeline: tile n mma overlaps tile n-1 epilogue
    tile_step<false>(acc0, acc1, rowsum, 0, sA, sB0, sB1, a_off, b_off, colbase, tid, L2E, ebias);
    #pragma unroll 1
    for (int n = 1; n < TILES - 1; n += 2) {
        tile_step<true>(acc1, acc0, rowsum, n,     sA, sB0, sB1, a_off, b_off, colbase, tid, L2E, ebias);
        tile_step<true>(acc0, acc1, rowsum, n + 1, sA, sB0, sB1, a_off, b_off, colbase, tid, L2E, ebias);
    }
    tile_step<true>(acc1, acc0, rowsum, TILES - 1, sA, sB0, sB1, a_off, b_off, colbase, tid, L2E, ebias);
    // drain last tile's epilogue
    #pragma unroll
    for (int v = 0; v < 64; v++) {
        int mi = v >> 4, nj = (v >> 2) & 3, c = v & 3;
        rowsum[mi * 2 + (c >> 1)] += ex2f(fmaf(acc1[mi][nj][c], L2E, ebias));
    }

    // reduce: lanes sharing a row differ in bits 0-1
    #pragma unroll
    for (int i = 0; i < 8; i++) {
        rowsum[i] += __shfl_xor_sync(0xffffffffu, rowsum[i], 1);
        rowsum[i] += __shfl_xor_sync(0xffffffffu, rowsum[i], 2);
    }
    float* red = (float*)smem;   // reuse A area (compute done; synced above)
    if ((lane & 3) == 0) {
        int g = lane >> 2;
        #pragma unroll
        for (int i = 0; i < 8; i++) {
            int row = warp_m * 64 + (i >> 1) * 16 + g + (i & 1) * 8;
            red[row * 4 + warp_n] = rowsum[i];
        }
    }
    __syncthreads();
    if (tid < GBM) {
        float s = red[tid * 4] + red[tid * 4 + 1] + red[tid * 4 + 2] + red[tid * 4 + 3];
        g_psum[slice * BDIM + row0 + tid] = s;
    }
    __threadfence();
    __syncthreads();
    if (tid == 0)
        s_last = (atomicAdd(&g_done[panel], 1) == NSLICE - 1);
    __syncthreads();

    if (s_last) {
        __threadfence();
        if (tid < GBM) {
            int row = row0 + tid;
            float S = 0.f;
            #pragma unroll
            for (int sl = 0; sl < NSLICE; sl++) S += g_psum[sl * BDIM + row];
            float o = Mconst + logf(S) - g_diag[row] * Mconst - logf((float)BDIM);
            out[row] = fminf(fmaxf(o, -5.f), 15.f);
        }
    }
}

// ---------------------------------------------------------------------------
extern "C" void kernel_launch(void* const* d_in, const int* in_sizes, int n_in,
                              void* d_out, int out_size) {
    const float* z       = (const float*)d_in[0];
    const float* t       = (const float*)d_in[1];
    const float* e       = (const float*)d_in[2];
    const float* log_tau = (const float*)d_in[3];
    const float* E       = (const float*)d_in[4];
    const float* L       = (const float*)d_in[5];
    float* out = (float*)d_out;

    const int smem_sz = 3 * TILE_BYTES;   // 202,752 B
    cudaFuncSetAttribute(gemm_lse_mma, cudaFuncAttributeMaxDynamicSharedMemorySize, smem_sz);

    suffix_kernel<<<MDIM, MDIM>>>(E);
    prep_kernel<<<BDIM / 8, 256>>>(z, t, e, log_tau, E, L);
    gemm_lse_mma<<<dim3(NSLICE, NPANEL), 256, smem_sz>>>(log_tau, out);
}